// round 15
// baseline (speedup 1.0000x reference)
#include <cuda_runtime.h>
#include <cstdint>

#define D     128
#define NN    512
#define BB    4
#define ROWS  16      // rows per row block
#define NFOLD 4       // fold blocks (one per batch)
#define NROW  128u    // row blocks (1/SM)
#define NBLK  (NROW + NFOLD)   // 132 <= 148 SMs, all wave-1 resident
#define BPB   32u     // row blocks per batch

// Scratch (device globals — no allocation allowed). All counters are
// MONOTONIC across graph replays (epoch-based waits, no resets needed).
__device__ float2  g_vb[BB][D];       // per batch, per e: {v1, base}
__device__ float   g_r[BB * NN * 4];  // per row: li0 li1 lj0 lj1
__device__ unsigned g_vbready[BB] = {0u, 0u, 0u, 0u};
__device__ unsigned g_batch[BB]   = {0u, 0u, 0u, 0u};
__device__ unsigned g_launch = 0u;    // row-block ticket -> epoch = ticket/128

// dynamic smem floats: W2 16384 | h 2048 | Hf 2048 | Wc 512 | p 16 | li 32
#define OFF_W2 0
#define OFF_H  16384
#define OFF_HF (16384 + 2048)
#define OFF_WC (16384 + 2048 + 2048)
#define OFF_P  (16384 + 2048 + 2048 + 512)
#define OFF_LI (16384 + 2048 + 2048 + 512 + 16)
#define SMEM_FLOATS (16384 + 2048 + 2048 + 512 + 16 + 32)

__global__ void __launch_bounds__(256, 2)
fused_kernel(const int*   __restrict__ adj,
             const int*   __restrict__ t,
             const float* __restrict__ TE,
             const float* __restrict__ nc,
             const float* __restrict__ EE,
             const float* __restrict__ W1,
             const float* __restrict__ b1,
             const float* __restrict__ W2,
             const float* __restrict__ b2,
             const float* __restrict__ Wc,
             const float* __restrict__ bc,
             float*       __restrict__ out)
{
    const int tid = threadIdx.x;
    const int bid = blockIdx.x;

    // ================= FOLD BLOCKS (bid 0..3): compute (v1, base_b) =========
    if (bid < NFOLD) {
        const int b = bid;
        __shared__ float sA0[D], sAd[D], sB[D], sC[D], sSum[D];

        // t[b] issued FIRST (head of the serial chain t -> TE row).
        int tb = t[b];
        float b1e = (tid < 128) ? b1[tid] : 0.f;

        if (tid < 128) {
            float e0 = EE[tid], e1 = EE[D + tid];
            sA0[tid] = e0;
            sAd[tid] = e1 - e0;
        } else {
            int f = tid - 128;
            sB[f] = nc[f];
            sC[f] = TE[(size_t)tb * D + f];
        }
        __syncthreads();

        const int e = tid & 127;
        if (tid < 128) {
            // W1A column-e dots: base part (E0) and v1 (E1-E0). One load, 2 FMA.
            const float* W = W1 + e;
            float a0 = 0.f, a1 = 0.f;
#pragma unroll 8
            for (int f = 0; f < D; f++) {
                float w = W[(size_t)f * D];
                a0 = fmaf(sA0[f], w, a0);
                a1 = fmaf(sAd[f], w, a1);
            }
            __syncthreads();               // wait for sSum from upper half
            float base = a0 + sSum[e] + b1e;
            g_vb[b][e] = make_float2(a1, base);
            __threadfence();               // release
        } else {
            // W1B (nc) + W1C (TE) column-e dots, independent accumulators.
            const float* Wb = W1 + (size_t)D * D + e;
            const float* Wq = W1 + (size_t)2 * D * D + e;
            float aB = 0.f, aC = 0.f;
#pragma unroll 8
            for (int f = 0; f < D; f++) {
                aB = fmaf(sB[f], Wb[(size_t)f * D], aB);
                aC = fmaf(sC[f], Wq[(size_t)f * D], aC);
            }
            sSum[e] = aB + aC;
            __syncthreads();
        }
        __syncthreads();
        if (tid == 0) atomicAdd(&g_vbready[b], 1u);
        return;                            // fold blocks do NO row work
    }

    // ================= ROW BLOCKS (bid 4..131) ==============================
    extern __shared__ float smem[];
    float* W2s  = smem + OFF_W2;   // [d][128]
    float* h_s  = smem + OFF_H;    // [d][16]
    float* Hfs  = smem + OFF_HF;   // [r][128]
    float* Wcs  = smem + OFF_WC;   // [e][4]
    float* p_s  = smem + OFF_P;    // [16]
    float* li_s = smem + OFF_LI;   // [16][2]

    const int rb    = bid - NFOLD;         // 0..127
    const int b     = rb >> 5;             // batch
    const int i0    = (rb & 31) * ROWS;
    const int grow0 = b * NN + i0;

    const int warp = tid >> 5;             // 0..7
    const int lane = tid & 31;
    const int e    = tid & 127;
    const int g    = tid >> 7;             // 0/1: 8-row half

    // Epoch ticket (tid0 register only) — overlapped with everything below.
    unsigned epoch = 0u;
    if (tid == 0) epoch = atomicAdd(&g_launch, 1u) >> 7;   // /128

    // Long-lived scalars issued at entry.
    const float b2e = b2[e];
    const float bc0 = bc[0], bc1 = bc[1];

    // adj row-sums first (longest DRAM latency): warp w -> rows 2w, 2w+1.
    {
#pragma unroll
        for (int rr = 0; rr < 2; rr++) {
            int row = 2 * warp + rr;
            const int4* a4 = (const int4*)adj + (size_t)(grow0 + row) * (NN / 4);
            int s = 0;
#pragma unroll
            for (int k = 0; k < 4; k++) {
                int4 v = a4[k * 32 + lane];
                s += v.x + v.y + v.z + v.w;
            }
#pragma unroll
            for (int o = 16; o; o >>= 1) s += __shfl_xor_sync(0xffffffffu, s, o);
            if (lane == 0) p_s[row] = (float)s * (1.0f / 512.0f);
        }
    }

    // Stage full W2 (64KB, coalesced float4) + Wc.
    {
        const float4* W2_4 = (const float4*)W2;
        float4* W2s_4 = (float4*)W2s;
#pragma unroll
        for (int k = 0; k < 16; k++) W2s_4[tid + k * 256] = W2_4[tid + k * 256];
    }
    if (g == 0) {
        float4 wc = make_float4(Wc[e * 2 + 0], Wc[e * 2 + 1],
                                Wc[(D + e) * 2 + 0], Wc[(D + e) * 2 + 1]);
        *(float4*)(Wcs + e * 4) = wc;
    }

    // Wait for this batch's fold block (pure spin, epoch target).
    if (tid == 0) {
        while (*(volatile unsigned*)&g_vbready[b] < epoch + 1u) { }
        __threadfence();                   // acquire
    }
    __syncthreads();

    // h: single float2 L2 load gives (v1, base) at dim e; 8 rows per half.
    {
        float2 vb = *(const float2*)(&g_vb[b][e]);
        float hv[8];
#pragma unroll
        for (int r = 0; r < 8; r++)
            hv[r] = fmaxf(fmaf(p_s[g * 8 + r], vb.x, vb.y), 0.f);
        float4* dst = (float4*)(h_s + e * ROWS + g * 8);
        dst[0] = make_float4(hv[0], hv[1], hv[2], hv[3]);
        dst[1] = make_float4(hv[4], hv[5], hv[6], hv[7]);
    }
    __syncthreads();

    // Matvec: thread (e,g) computes Hf[r][e] for its 8 rows via f32x2.
    unsigned long long acc0, acc1, acc2, acc3;
    {
        unsigned int ub = __float_as_uint(b2e);
        asm("mov.b64 %0, {%1, %1};" : "=l"(acc0) : "r"(ub));
        acc1 = acc0; acc2 = acc0; acc3 = acc0;
    }
#pragma unroll 8
    for (int d = 0; d < D; d++) {
        float w = W2s[d * D + e];
        const ulonglong2* hp = (const ulonglong2*)(h_s + d * ROWS + g * 8); // uniform
        ulonglong2 ha = hp[0];
        ulonglong2 hb = hp[1];
        unsigned long long w2;
        asm("mov.b64 %0, {%1, %1};" : "=l"(w2) : "r"(__float_as_uint(w)));
        asm("fma.rn.f32x2 %0, %1, %2, %0;" : "+l"(acc0) : "l"(w2), "l"(ha.x));
        asm("fma.rn.f32x2 %0, %1, %2, %0;" : "+l"(acc1) : "l"(w2), "l"(ha.y));
        asm("fma.rn.f32x2 %0, %1, %2, %0;" : "+l"(acc2) : "l"(w2), "l"(hb.x));
        asm("fma.rn.f32x2 %0, %1, %2, %0;" : "+l"(acc3) : "l"(w2), "l"(hb.y));
    }
    {
        float2 f0 = *(float2*)&acc0;
        float2 f1 = *(float2*)&acc1;
        float2 f2 = *(float2*)&acc2;
        float2 f3 = *(float2*)&acc3;
        Hfs[(g * 8 + 0) * D + e] = fmaxf(f0.x, 0.f);
        Hfs[(g * 8 + 1) * D + e] = fmaxf(f0.y, 0.f);
        Hfs[(g * 8 + 2) * D + e] = fmaxf(f1.x, 0.f);
        Hfs[(g * 8 + 3) * D + e] = fmaxf(f1.y, 0.f);
        Hfs[(g * 8 + 4) * D + e] = fmaxf(f2.x, 0.f);
        Hfs[(g * 8 + 5) * D + e] = fmaxf(f2.y, 0.f);
        Hfs[(g * 8 + 6) * D + e] = fmaxf(f3.x, 0.f);
        Hfs[(g * 8 + 7) * D + e] = fmaxf(f3.y, 0.f);
    }
    __syncthreads();

    // Reduce: warp w -> rows 2w, 2w+1; keep own li in smem for expand.
    {
#pragma unroll
        for (int rr = 0; rr < 2; rr++) {
            int r = 2 * warp + rr;
            float s0 = 0.f, s1 = 0.f, s2 = 0.f, s3 = 0.f;
#pragma unroll
            for (int k = 0; k < 4; k++) {
                int ee = lane + 32 * k;
                float hv = Hfs[r * D + ee];
                float4 wc = *(const float4*)(Wcs + ee * 4);
                s0 = fmaf(hv, wc.x, s0);
                s1 = fmaf(hv, wc.y, s1);
                s2 = fmaf(hv, wc.z, s2);
                s3 = fmaf(hv, wc.w, s3);
            }
#pragma unroll
            for (int o = 16; o; o >>= 1) {
                s0 += __shfl_xor_sync(0xffffffffu, s0, o);
                s1 += __shfl_xor_sync(0xffffffffu, s1, o);
                s2 += __shfl_xor_sync(0xffffffffu, s2, o);
                s3 += __shfl_xor_sync(0xffffffffu, s3, o);
            }
            if (lane == 0) {
                *(float4*)(g_r + (size_t)(grow0 + r) * 4) = make_float4(s0, s1, s2, s3);
                *(float2*)(li_s + r * 2) = make_float2(s0, s1);
                __threadfence();           // release g_r writes
            }
        }
    }
    __syncthreads();

    // Publish + wait for own batch's 32 row blocks (epoch target).
    if (tid == 0) {
        atomicAdd(&g_batch[b], 1u);
        unsigned target = (epoch + 1u) * BPB;
        while (*(volatile unsigned*)&g_batch[b] < target) { }
        __threadfence();                   // acquire
    }
    __syncthreads();

    // Expand (register path): thread tid owns column pair 2tid, 2tid+1.
    {
        const size_t jbase = (size_t)(b * NN + 2 * tid) * 4 + 2;
        float2 ljA = *(const float2*)(g_r + jbase);
        float2 ljB = *(const float2*)(g_r + jbase + 4);
        const float ax = ljA.x + bc0, ay = ljA.y + bc1;
        const float az = ljB.x + bc0, aw = ljB.y + bc1;

        float4* out4 = (float4*)out;
#pragma unroll
        for (int r = 0; r < ROWS; r++) {
            float2 li = *(const float2*)(li_s + r * 2);
            out4[(size_t)(grow0 + r) * 256 + tid] =
                make_float4(li.x + ax, li.y + ay, li.x + az, li.y + aw);
        }
    }
    // No reset tail: epoch-based flags are monotonic across replays.
}

// ---------------------------------------------------------------------------
extern "C" void kernel_launch(void* const* d_in, const int* in_sizes, int n_in,
                              void* d_out, int out_size)
{
    const int*   adj = (const int*)d_in[0];
    const int*   t   = (const int*)d_in[1];
    const float* TE  = (const float*)d_in[2];
    const float* nc  = (const float*)d_in[3];
    const float* EE  = (const float*)d_in[4];
    const float* W1  = (const float*)d_in[5];
    const float* b1  = (const float*)d_in[6];
    const float* W2  = (const float*)d_in[7];
    const float* b2  = (const float*)d_in[8];
    const float* Wc  = (const float*)d_in[9];
    const float* bc  = (const float*)d_in[10];
    float* out = (float*)d_out;

    (void)in_sizes; (void)n_in; (void)out_size;

    const int smem_b = SMEM_FLOATS * sizeof(float);
    cudaFuncSetAttribute(fused_kernel, cudaFuncAttributeMaxDynamicSharedMemorySize, smem_b);

    fused_kernel<<<NBLK, 256, smem_b>>>(adj, t, TE, nc, EE, W1, b1, W2, b2, Wc, bc, out);
}

// round 16
// speedup vs baseline: 1.1380x; 1.1380x over previous
#include <cuda_runtime.h>
#include <cstdint>

#define D     128
#define NN    512
#define BB    4
#define ROWS  16      // rows per block
#define NPROD 56u     // fold producer count (7 jobs x 8 f-chunks)
#define NBLK  128u    // one block per SM -> no wave imbalance
#define WPB   8       // warps per block
#define ARR_PER_BATCH 256u   // 32 blocks x 8 warp-arrivals

// Scratch (device globals). All counters MONOTONIC across replays (epoch waits).
__device__ float g_part[56 * D];       // W1 fold partials (indexed by pid)
__device__ float g_r[BB * NN * 4];     // per row: li0 li1 lj0 lj1
__device__ unsigned g_ready = 0u;      // fold completions (target: (ep+1)*56)
__device__ unsigned g_batch[BB] = {0u, 0u, 0u, 0u};  // warp arrivals per batch
__device__ unsigned g_launch = 0u;     // block ticket -> epoch = ticket/128

// smem floats: W2 16384 | h 2048 | Hf 2048 | Wc 512 | p 16 | li 32  (~84KB)
#define OFF_W2 0
#define OFF_H  16384
#define OFF_HF (16384 + 2048)
#define OFF_WC (16384 + 2048 + 2048)
#define OFF_P  (16384 + 2048 + 2048 + 512)
#define OFF_LI (16384 + 2048 + 2048 + 512 + 16)
#define SMEM_FLOATS (16384 + 2048 + 2048 + 512 + 16 + 32)

// ---------------------------------------------------------------------------
// ONE kernel, 128 blocks x 256 threads. Composite of every proven win:
//   epoch ticket + scalars at entry -> producers: t first, W1 prefetch under
//   t->TE chain, shallow 16-wide fold -> adj (DRAM hoisted) -> W2/Wc staging
//   -> pure-spin fold wait -> h -> f32x2 matvec -> reduce with PER-WARP early
//   publish -> pure-spin batch wait -> register expand. No reset tail.
// ---------------------------------------------------------------------------
__global__ void __launch_bounds__(256, 2)
fused_kernel(const int*   __restrict__ adj,
             const int*   __restrict__ t,
             const float* __restrict__ TE,
             const float* __restrict__ nc,
             const float* __restrict__ EE,
             const float* __restrict__ W1,
             const float* __restrict__ b1,
             const float* __restrict__ W2,
             const float* __restrict__ b2,
             const float* __restrict__ Wc,
             const float* __restrict__ bc,
             float*       __restrict__ out)
{
    extern __shared__ float smem[];
    float* W2s  = smem + OFF_W2;   // [d][128]
    float* h_s  = smem + OFF_H;    // [d][16]
    float* Hfs  = smem + OFF_HF;   // [r][128]
    float* Wcs  = smem + OFF_WC;   // [e][4]
    float* p_s  = smem + OFF_P;    // [16]
    float* li_s = smem + OFF_LI;   // [16][2]

    const int tid   = threadIdx.x;
    const int bid   = blockIdx.x;
    const int b     = bid >> 5;            // batch (32 blocks per batch)
    const int i0    = (bid & 31) * ROWS;
    const int grow0 = b * NN + i0;

    const int warp = tid >> 5;             // 0..7
    const int lane = tid & 31;
    const int e    = tid & 127;            // output column / hidden dim
    const int g    = tid >> 7;             // 0/1: 8-row half

    // Epoch ticket (tid0 reg only) + long-lived scalars, all issued at entry.
    unsigned epoch = 0u;
    if (tid == 0) epoch = atomicAdd(&g_launch, 1u) >> 7;
    const float b1e = b1[e];
    const float b2e = b2[e];
    const float bc0 = bc[0], bc1 = bc[1];

    // ---- producer role (even bids < 112 -> pid 0..55): t FIRST, W1 prefetch ----
    if ((bid & 1) == 0 && bid < 112) {
        const int pid = bid >> 1;          // 0..55
        __shared__ float s_coef[16];
        const int j  = pid >> 3;           // 0..6
        const int f0 = (pid & 7) * 16;
        int tb = (j >= 3) ? t[j - 3] : 0;  // head of the t->TE chain, issue #1
        float w[16];
        if (tid < 128) {
            const int blk = (j <= 1) ? 0 : (j == 2 ? 1 : 2);
            const float* W = W1 + ((size_t)blk * D + f0) * D + tid;
#pragma unroll
            for (int f = 0; f < 16; f++) w[f] = W[(size_t)f * D];  // overlaps t->TE
        }
        if (tid < 16) {
            int f = f0 + tid;
            float v;
            if (j == 0)      v = EE[D + f] - EE[f];
            else if (j == 1) v = EE[f];
            else if (j == 2) v = nc[f];
            else             v = TE[(size_t)tb * D + f];
            s_coef[tid] = v;
        }
        __syncthreads();
        if (tid < 128) {
            float acc = 0.f;
#pragma unroll
            for (int f = 0; f < 16; f++)
                acc = fmaf(s_coef[f], w[f], acc);
            g_part[pid * D + tid] = acc;
            __threadfence();               // release g_part
        }
        __syncthreads();
        if (tid == 0) atomicAdd(&g_ready, 1u);
    }

    // ---- adj row-sums: warp w -> rows 2w, 2w+1 (longest DRAM latency) ----
    {
#pragma unroll
        for (int rr = 0; rr < 2; rr++) {
            int row = 2 * warp + rr;
            const int4* a4 = (const int4*)adj + (size_t)(grow0 + row) * (NN / 4);
            int s = 0;
#pragma unroll
            for (int k = 0; k < 4; k++) {
                int4 v = a4[k * 32 + lane];
                s += v.x + v.y + v.z + v.w;
            }
#pragma unroll
            for (int o = 16; o; o >>= 1) s += __shfl_xor_sync(0xffffffffu, s, o);
            if (lane == 0) p_s[row] = (float)s * (1.0f / 512.0f);
        }
    }

    // ---- stage full W2 (64KB, coalesced float4) + Wc ----
    {
        const float4* W2_4 = (const float4*)W2;
        float4* W2s_4 = (float4*)W2s;
#pragma unroll
        for (int k = 0; k < 16; k++) W2s_4[tid + k * 256] = W2_4[tid + k * 256];
    }
    if (g == 0) {
        float4 wc = make_float4(Wc[e * 2 + 0], Wc[e * 2 + 1],
                                Wc[(D + e) * 2 + 0], Wc[(D + e) * 2 + 1]);
        *(float4*)(Wcs + e * 4) = wc;
    }

    // ---- wait for fold completion (pure spin, epoch target) ----
    if (tid == 0) {
        unsigned target = (epoch + 1u) * NPROD;
        while (*(volatile unsigned*)&g_ready < target) { }
        __threadfence();                   // acquire
    }
    __syncthreads();

    // Finalize v1/base at hidden dim d=e (32 independent L2-hot loads).
    {
        float v1d   = 0.f;
        float based = b1e;
#pragma unroll
        for (int c = 0; c < 8; c++) {
            v1d   += g_part[(0 * 8 + c) * D + e];
            based += g_part[(1 * 8 + c) * D + e]
                   + g_part[(2 * 8 + c) * D + e]
                   + g_part[((3 + b) * 8 + c) * D + e];
        }
        float hv[8];
#pragma unroll
        for (int r = 0; r < 8; r++)
            hv[r] = fmaxf(fmaf(p_s[g * 8 + r], v1d, based), 0.f);
        float4* dst = (float4*)(h_s + e * ROWS + g * 8);
        dst[0] = make_float4(hv[0], hv[1], hv[2], hv[3]);
        dst[1] = make_float4(hv[4], hv[5], hv[6], hv[7]);
    }
    __syncthreads();

    // Matvec: thread (e,g) computes Hf[r][e] for its 8 rows via f32x2.
    unsigned long long acc0, acc1, acc2, acc3;
    {
        unsigned int ub = __float_as_uint(b2e);
        asm("mov.b64 %0, {%1, %1};" : "=l"(acc0) : "r"(ub));
        acc1 = acc0; acc2 = acc0; acc3 = acc0;
    }
#pragma unroll 8
    for (int d = 0; d < D; d++) {
        float w = W2s[d * D + e];
        const ulonglong2* hp = (const ulonglong2*)(h_s + d * ROWS + g * 8); // uniform
        ulonglong2 ha = hp[0];
        ulonglong2 hb = hp[1];
        unsigned long long w2;
        asm("mov.b64 %0, {%1, %1};" : "=l"(w2) : "r"(__float_as_uint(w)));
        asm("fma.rn.f32x2 %0, %1, %2, %0;" : "+l"(acc0) : "l"(w2), "l"(ha.x));
        asm("fma.rn.f32x2 %0, %1, %2, %0;" : "+l"(acc1) : "l"(w2), "l"(ha.y));
        asm("fma.rn.f32x2 %0, %1, %2, %0;" : "+l"(acc2) : "l"(w2), "l"(hb.x));
        asm("fma.rn.f32x2 %0, %1, %2, %0;" : "+l"(acc3) : "l"(w2), "l"(hb.y));
    }
    {
        float2 f0 = *(float2*)&acc0;
        float2 f1 = *(float2*)&acc1;
        float2 f2 = *(float2*)&acc2;
        float2 f3 = *(float2*)&acc3;
        Hfs[(g * 8 + 0) * D + e] = fmaxf(f0.x, 0.f);
        Hfs[(g * 8 + 1) * D + e] = fmaxf(f0.y, 0.f);
        Hfs[(g * 8 + 2) * D + e] = fmaxf(f1.x, 0.f);
        Hfs[(g * 8 + 3) * D + e] = fmaxf(f1.y, 0.f);
        Hfs[(g * 8 + 4) * D + e] = fmaxf(f2.x, 0.f);
        Hfs[(g * 8 + 5) * D + e] = fmaxf(f2.y, 0.f);
        Hfs[(g * 8 + 6) * D + e] = fmaxf(f3.x, 0.f);
        Hfs[(g * 8 + 7) * D + e] = fmaxf(f3.y, 0.f);
    }
    __syncthreads();

    // Reduce: warp w -> rows 2w, 2w+1; PER-WARP early publish to g_batch[b].
    {
#pragma unroll
        for (int rr = 0; rr < 2; rr++) {
            int r = 2 * warp + rr;
            float s0 = 0.f, s1 = 0.f, s2 = 0.f, s3 = 0.f;
#pragma unroll
            for (int k = 0; k < 4; k++) {
                int ee = lane + 32 * k;
                float hv = Hfs[r * D + ee];
                float4 wc = *(const float4*)(Wcs + ee * 4);
                s0 = fmaf(hv, wc.x, s0);
                s1 = fmaf(hv, wc.y, s1);
                s2 = fmaf(hv, wc.z, s2);
                s3 = fmaf(hv, wc.w, s3);
            }
#pragma unroll
            for (int o = 16; o; o >>= 1) {
                s0 += __shfl_xor_sync(0xffffffffu, s0, o);
                s1 += __shfl_xor_sync(0xffffffffu, s1, o);
                s2 += __shfl_xor_sync(0xffffffffu, s2, o);
                s3 += __shfl_xor_sync(0xffffffffu, s3, o);
            }
            if (lane == 0) {
                *(float4*)(g_r + (size_t)(grow0 + r) * 4) = make_float4(s0, s1, s2, s3);
                *(float2*)(li_s + r * 2) = make_float2(s0, s1);
            }
        }
        // Warp publishes as soon as ITS two rows are globally visible.
        if (lane == 0) {
            __threadfence();               // release this warp's g_r rows
            atomicAdd(&g_batch[b], 1u);
        }
    }

    // ---- wait for own batch's 256 warp-arrivals (epoch target) ----
    if (tid == 0) {
        unsigned target = (epoch + 1u) * ARR_PER_BATCH;
        while (*(volatile unsigned*)&g_batch[b] < target) { }
        __threadfence();                   // acquire
    }
    __syncthreads();                       // also covers li_s visibility

    // ---- expand (register path): thread tid owns column pair 2tid, 2tid+1 ----
    {
        const size_t jbase = (size_t)(b * NN + 2 * tid) * 4 + 2;
        float2 ljA = *(const float2*)(g_r + jbase);
        float2 ljB = *(const float2*)(g_r + jbase + 4);
        const float ax = ljA.x + bc0, ay = ljA.y + bc1;
        const float az = ljB.x + bc0, aw = ljB.y + bc1;

        float4* out4 = (float4*)out;
#pragma unroll
        for (int r = 0; r < ROWS; r++) {
            float2 li = *(const float2*)(li_s + r * 2);
            out4[(size_t)(grow0 + r) * 256 + tid] =
                make_float4(li.x + ax, li.y + ay, li.x + az, li.y + aw);
        }
    }
    // No reset tail: epoch-based flags are monotonic across replays.
}

// ---------------------------------------------------------------------------
extern "C" void kernel_launch(void* const* d_in, const int* in_sizes, int n_in,
                              void* d_out, int out_size)
{
    const int*   adj = (const int*)d_in[0];
    const int*   t   = (const int*)d_in[1];
    const float* TE  = (const float*)d_in[2];
    const float* nc  = (const float*)d_in[3];
    const float* EE  = (const float*)d_in[4];
    const float* W1  = (const float*)d_in[5];
    const float* b1  = (const float*)d_in[6];
    const float* W2  = (const float*)d_in[7];
    const float* b2  = (const float*)d_in[8];
    const float* Wc  = (const float*)d_in[9];
    const float* bc  = (const float*)d_in[10];
    float* out = (float*)d_out;

    (void)in_sizes; (void)n_in; (void)out_size;

    const int smem_b = SMEM_FLOATS * sizeof(float);
    cudaFuncSetAttribute(fused_kernel, cudaFuncAttributeMaxDynamicSharedMemorySize, smem_b);

    fused_kernel<<<NBLK, 256, smem_b>>>(adj, t, TE, nc, EE, W1, b1, W2, b2, Wc, bc, out);
}

// round 17
// speedup vs baseline: 1.1577x; 1.0173x over previous
#include <cuda_runtime.h>
#include <cstdint>

#define D     128
#define NN    512
#define BB    4
#define ROWS  16      // rows per block
#define NPROD 112u    // fold producers (7 jobs x 16 f-chunks of 8)
#define NBLK  128u    // one block per SM -> no wave imbalance
#define ARR_PER_BATCH 256u   // 32 blocks x 8 warp-arrivals

// Scratch (device globals). All counters MONOTONIC across replays (epoch waits).
__device__ float g_part[112 * D];      // W1 fold partials (indexed by pid)
__device__ float g_r[BB * NN * 4];     // per row: li0 li1 lj0 lj1
__device__ unsigned g_ready = 0u;      // fold completions (target: (ep+1)*112)
__device__ unsigned g_batch[BB] = {0u, 0u, 0u, 0u};  // warp arrivals per batch
__device__ unsigned g_launch = 0u;     // block ticket -> epoch = ticket/128

// smem floats: W2 16384 | h 2048 | Hf 2048 | Wc 512 | p 16 | li 32  (~84KB)
#define OFF_W2 0
#define OFF_H  16384
#define OFF_HF (16384 + 2048)
#define OFF_WC (16384 + 2048 + 2048)
#define OFF_P  (16384 + 2048 + 2048 + 512)
#define OFF_LI (16384 + 2048 + 2048 + 512 + 16)
#define SMEM_FLOATS (16384 + 2048 + 2048 + 512 + 16 + 32)

// ---------------------------------------------------------------------------
// ONE kernel, 128 blocks x 256 threads. R16 composite plus:
//   - 112 uniform producers ((bid&7)!=7 -> 28/batch), 8-wide shallow fold
//   - matvec split into two 64-deep halves (8 accumulators) to halve the
//     dependent-FMA chain.
// ---------------------------------------------------------------------------
__global__ void __launch_bounds__(256, 2)
fused_kernel(const int*   __restrict__ adj,
             const int*   __restrict__ t,
             const float* __restrict__ TE,
             const float* __restrict__ nc,
             const float* __restrict__ EE,
             const float* __restrict__ W1,
             const float* __restrict__ b1,
             const float* __restrict__ W2,
             const float* __restrict__ b2,
             const float* __restrict__ Wc,
             const float* __restrict__ bc,
             float*       __restrict__ out)
{
    extern __shared__ float smem[];
    float* W2s  = smem + OFF_W2;   // [d][128]
    float* h_s  = smem + OFF_H;    // [d][16]
    float* Hfs  = smem + OFF_HF;   // [r][128]
    float* Wcs  = smem + OFF_WC;   // [e][4]
    float* p_s  = smem + OFF_P;    // [16]
    float* li_s = smem + OFF_LI;   // [16][2]

    const int tid   = threadIdx.x;
    const int bid   = blockIdx.x;
    const int b     = bid >> 5;            // batch (32 blocks per batch)
    const int i0    = (bid & 31) * ROWS;
    const int grow0 = b * NN + i0;

    const int warp = tid >> 5;             // 0..7
    const int lane = tid & 31;
    const int e    = tid & 127;            // output column / hidden dim
    const int g    = tid >> 7;             // 0/1: 8-row half

    // Epoch ticket (tid0 reg only) + long-lived scalars, all issued at entry.
    unsigned epoch = 0u;
    if (tid == 0) epoch = atomicAdd(&g_launch, 1u) >> 7;
    const float b1e = b1[e];
    const float b2e = b2[e];
    const float bc0 = bc[0], bc1 = bc[1];

    // ---- producer role: (bid&7)!=7 -> 112 producers, 28 per batch ----
    // pid = bid - bid/8; job j = pid/16, chunk c = pid%16 (8 f-values).
    if ((bid & 7) != 7) {
        const int pid = bid - (bid >> 3);  // 0..111
        __shared__ float s_coef[8];
        const int j  = pid >> 4;           // 0..6
        const int f0 = (pid & 15) * 8;
        int tb = (j >= 3) ? t[j - 3] : 0;  // head of t->TE chain, issued first
        float w[8];
        if (tid < 128) {
            const int blk = (j <= 1) ? 0 : (j == 2 ? 1 : 2);
            const float* W = W1 + ((size_t)blk * D + f0) * D + tid;
#pragma unroll
            for (int f = 0; f < 8; f++) w[f] = W[(size_t)f * D];  // overlaps t->TE
        }
        if (tid < 8) {
            int f = f0 + tid;
            float v;
            if (j == 0)      v = EE[D + f] - EE[f];
            else if (j == 1) v = EE[f];
            else if (j == 2) v = nc[f];
            else             v = TE[(size_t)tb * D + f];
            s_coef[tid] = v;
        }
        __syncthreads();
        if (tid < 128) {
            float acc = 0.f;
#pragma unroll
            for (int f = 0; f < 8; f++)
                acc = fmaf(s_coef[f], w[f], acc);
            g_part[pid * D + tid] = acc;
            __threadfence();               // release g_part
        }
        __syncthreads();
        if (tid == 0) atomicAdd(&g_ready, 1u);
    }

    // ---- adj row-sums: warp w -> rows 2w, 2w+1 (longest DRAM latency) ----
    {
#pragma unroll
        for (int rr = 0; rr < 2; rr++) {
            int row = 2 * warp + rr;
            const int4* a4 = (const int4*)adj + (size_t)(grow0 + row) * (NN / 4);
            int s = 0;
#pragma unroll
            for (int k = 0; k < 4; k++) {
                int4 v = a4[k * 32 + lane];
                s += v.x + v.y + v.z + v.w;
            }
#pragma unroll
            for (int o = 16; o; o >>= 1) s += __shfl_xor_sync(0xffffffffu, s, o);
            if (lane == 0) p_s[row] = (float)s * (1.0f / 512.0f);
        }
    }

    // ---- stage full W2 (64KB, coalesced float4) + Wc ----
    {
        const float4* W2_4 = (const float4*)W2;
        float4* W2s_4 = (float4*)W2s;
#pragma unroll
        for (int k = 0; k < 16; k++) W2s_4[tid + k * 256] = W2_4[tid + k * 256];
    }
    if (g == 0) {
        float4 wc = make_float4(Wc[e * 2 + 0], Wc[e * 2 + 1],
                                Wc[(D + e) * 2 + 0], Wc[(D + e) * 2 + 1]);
        *(float4*)(Wcs + e * 4) = wc;
    }

    // ---- wait for fold completion (pure spin, epoch target) ----
    if (tid == 0) {
        unsigned target = (epoch + 1u) * NPROD;
        while (*(volatile unsigned*)&g_ready < target) { }
        __threadfence();                   // acquire
    }
    __syncthreads();

    // Finalize v1/base at hidden dim d=e (64 independent L2-hot loads, 1 wave).
    {
        float v1d   = 0.f;
        float based = b1e;
#pragma unroll
        for (int c = 0; c < 16; c++) {
            v1d   += g_part[(0 * 16 + c) * D + e];
            based += g_part[(1 * 16 + c) * D + e]
                   + g_part[(2 * 16 + c) * D + e]
                   + g_part[((3 + b) * 16 + c) * D + e];
        }
        float hv[8];
#pragma unroll
        for (int r = 0; r < 8; r++)
            hv[r] = fmaxf(fmaf(p_s[g * 8 + r], v1d, based), 0.f);
        float4* dst = (float4*)(h_s + e * ROWS + g * 8);
        dst[0] = make_float4(hv[0], hv[1], hv[2], hv[3]);
        dst[1] = make_float4(hv[4], hv[5], hv[6], hv[7]);
    }
    __syncthreads();

    // Matvec: two 64-deep halves with separate accumulators (halved chain).
    unsigned long long a0A, a1A, a2A, a3A, a0B, a1B, a2B, a3B;
    {
        unsigned int ub = __float_as_uint(b2e);
        asm("mov.b64 %0, {%1, %1};" : "=l"(a0A) : "r"(ub));
        a1A = a0A; a2A = a0A; a3A = a0A;
        unsigned long long z = 0ull;
        a0B = z; a1B = z; a2B = z; a3B = z;
    }
#pragma unroll 8
    for (int d = 0; d < 64; d++) {
        float wA = W2s[d * D + e];
        float wB = W2s[(d + 64) * D + e];
        const ulonglong2* hpA = (const ulonglong2*)(h_s + d * ROWS + g * 8);
        const ulonglong2* hpB = (const ulonglong2*)(h_s + (d + 64) * ROWS + g * 8);
        ulonglong2 haA = hpA[0], hbA = hpA[1];
        ulonglong2 haB = hpB[0], hbB = hpB[1];
        unsigned long long w2A, w2B;
        asm("mov.b64 %0, {%1, %1};" : "=l"(w2A) : "r"(__float_as_uint(wA)));
        asm("mov.b64 %0, {%1, %1};" : "=l"(w2B) : "r"(__float_as_uint(wB)));
        asm("fma.rn.f32x2 %0, %1, %2, %0;" : "+l"(a0A) : "l"(w2A), "l"(haA.x));
        asm("fma.rn.f32x2 %0, %1, %2, %0;" : "+l"(a1A) : "l"(w2A), "l"(haA.y));
        asm("fma.rn.f32x2 %0, %1, %2, %0;" : "+l"(a2A) : "l"(w2A), "l"(hbA.x));
        asm("fma.rn.f32x2 %0, %1, %2, %0;" : "+l"(a3A) : "l"(w2A), "l"(hbA.y));
        asm("fma.rn.f32x2 %0, %1, %2, %0;" : "+l"(a0B) : "l"(w2B), "l"(haB.x));
        asm("fma.rn.f32x2 %0, %1, %2, %0;" : "+l"(a1B) : "l"(w2B), "l"(haB.y));
        asm("fma.rn.f32x2 %0, %1, %2, %0;" : "+l"(a2B) : "l"(w2B), "l"(hbB.x));
        asm("fma.rn.f32x2 %0, %1, %2, %0;" : "+l"(a3B) : "l"(w2B), "l"(hbB.y));
    }
    {
        asm("add.rn.f32x2 %0, %0, %1;" : "+l"(a0A) : "l"(a0B));
        asm("add.rn.f32x2 %0, %0, %1;" : "+l"(a1A) : "l"(a1B));
        asm("add.rn.f32x2 %0, %0, %1;" : "+l"(a2A) : "l"(a2B));
        asm("add.rn.f32x2 %0, %0, %1;" : "+l"(a3A) : "l"(a3B));
        float2 f0 = *(float2*)&a0A;
        float2 f1 = *(float2*)&a1A;
        float2 f2 = *(float2*)&a2A;
        float2 f3 = *(float2*)&a3A;
        Hfs[(g * 8 + 0) * D + e] = fmaxf(f0.x, 0.f);
        Hfs[(g * 8 + 1) * D + e] = fmaxf(f0.y, 0.f);
        Hfs[(g * 8 + 2) * D + e] = fmaxf(f1.x, 0.f);
        Hfs[(g * 8 + 3) * D + e] = fmaxf(f1.y, 0.f);
        Hfs[(g * 8 + 4) * D + e] = fmaxf(f2.x, 0.f);
        Hfs[(g * 8 + 5) * D + e] = fmaxf(f2.y, 0.f);
        Hfs[(g * 8 + 6) * D + e] = fmaxf(f3.x, 0.f);
        Hfs[(g * 8 + 7) * D + e] = fmaxf(f3.y, 0.f);
    }
    __syncthreads();

    // Reduce: warp w -> rows 2w, 2w+1; PER-WARP early publish to g_batch[b].
    {
#pragma unroll
        for (int rr = 0; rr < 2; rr++) {
            int r = 2 * warp + rr;
            float s0 = 0.f, s1 = 0.f, s2 = 0.f, s3 = 0.f;
#pragma unroll
            for (int k = 0; k < 4; k++) {
                int ee = lane + 32 * k;
                float hv = Hfs[r * D + ee];
                float4 wc = *(const float4*)(Wcs + ee * 4);
                s0 = fmaf(hv, wc.x, s0);
                s1 = fmaf(hv, wc.y, s1);
                s2 = fmaf(hv, wc.z, s2);
                s3 = fmaf(hv, wc.w, s3);
            }
#pragma unroll
            for (int o = 16; o; o >>= 1) {
                s0 += __shfl_xor_sync(0xffffffffu, s0, o);
                s1 += __shfl_xor_sync(0xffffffffu, s1, o);
                s2 += __shfl_xor_sync(0xffffffffu, s2, o);
                s3 += __shfl_xor_sync(0xffffffffu, s3, o);
            }
            if (lane == 0) {
                *(float4*)(g_r + (size_t)(grow0 + r) * 4) = make_float4(s0, s1, s2, s3);
                *(float2*)(li_s + r * 2) = make_float2(s0, s1);
            }
        }
        // Warp publishes as soon as ITS two rows are globally visible.
        if (lane == 0) {
            __threadfence();               // release this warp's g_r rows
            atomicAdd(&g_batch[b], 1u);
        }
    }

    // ---- wait for own batch's 256 warp-arrivals (epoch target) ----
    if (tid == 0) {
        unsigned target = (epoch + 1u) * ARR_PER_BATCH;
        while (*(volatile unsigned*)&g_batch[b] < target) { }
        __threadfence();                   // acquire
    }
    __syncthreads();                       // also covers li_s visibility

    // ---- expand (register path): thread tid owns column pair 2tid, 2tid+1 ----
    {
        const size_t jbase = (size_t)(b * NN + 2 * tid) * 4 + 2;
        float2 ljA = *(const float2*)(g_r + jbase);
        float2 ljB = *(const float2*)(g_r + jbase + 4);
        const float ax = ljA.x + bc0, ay = ljA.y + bc1;
        const float az = ljB.x + bc0, aw = ljB.y + bc1;

        float4* out4 = (float4*)out;
#pragma unroll
        for (int r = 0; r < ROWS; r++) {
            float2 li = *(const float2*)(li_s + r * 2);
            out4[(size_t)(grow0 + r) * 256 + tid] =
                make_float4(li.x + ax, li.y + ay, li.x + az, li.y + aw);
        }
    }
    // No reset tail: epoch-based flags are monotonic across replays.
}

// ---------------------------------------------------------------------------
extern "C" void kernel_launch(void* const* d_in, const int* in_sizes, int n_in,
                              void* d_out, int out_size)
{
    const int*   adj = (const int*)d_in[0];
    const int*   t   = (const int*)d_in[1];
    const float* TE  = (const float*)d_in[2];
    const float* nc  = (const float*)d_in[3];
    const float* EE  = (const float*)d_in[4];
    const float* W1  = (const float*)d_in[5];
    const float* b1  = (const float*)d_in[6];
    const float* W2  = (const float*)d_in[7];
    const float* b2  = (const float*)d_in[8];
    const float* Wc  = (const float*)d_in[9];
    const float* bc  = (const float*)d_in[10];
    float* out = (float*)d_out;

    (void)in_sizes; (void)n_in; (void)out_size;

    const int smem_b = SMEM_FLOATS * sizeof(float);
    cudaFuncSetAttribute(fused_kernel, cudaFuncAttributeMaxDynamicSharedMemorySize, smem_b);

    fused_kernel<<<NBLK, 256, smem_b>>>(adj, t, TE, nc, EE, W1, b1, W2, b2, Wc, bc, out);
}